// round 1
// baseline (speedup 1.0000x reference)
#include <cuda_runtime.h>
#include <cuda_bf16.h>
#include <math.h>

// Problem constants
#define BATCH 2
#define SEQ   2048
#define DMODEL 2048
#define NH    16
#define NKV   4
#define HD    128
#define ROPE  64
#define MTOK  (BATCH*SEQ)          // 4096 tokens
#define EPSV  1.1920929e-07f

// ---------------- scratch (device globals; allocation-free) ----------------
__device__ float g_Qb[(long long)MTOK * DMODEL];          // 32 MB  q proj out [m, h*128+d]
__device__ float g_Kb[(long long)MTOK * (NKV*HD)];        // 8 MB
__device__ float g_Vb[(long long)MTOK * (NKV*HD)];        // 8 MB
__device__ float g_Qp[(long long)BATCH*NH  * SEQ * HD];   // 32 MB  [b,h,s,d]
__device__ float g_Kp[(long long)BATCH*NKV * SEQ * HD];   // 8 MB
__device__ float g_Vp[(long long)BATCH*NKV * SEQ * HD];   // 8 MB
__device__ float g_S [(long long)BATCH*NH  * SEQ * SEQ];  // 537 MB scores / probs
__device__ float g_Y [(long long)MTOK * DMODEL];          // 32 MB  attn out [b,s,h*128+d]

// ---------------- generic 128x128 register-tiled SGEMM ----------------
// C[m,n] = alpha * sum_k A[m,k] * B(k,n)     (B(k,n)=B[n,k] if TRANS_B)
// batch z: A += z*strideA; B += (z/bDiv)*strideB; C += (z/cDiv)*strideC + (z%cDiv)*strideC2
// CAUSAL: write -1e30 where n>m (global in-batch indices); fully masked tiles skip work.
// CAUSAL_K: bound K loop at m0+128 (for P*V where P is zero beyond the diagonal).
template<bool TRANS_B, bool CAUSAL, bool CAUSAL_K>
__global__ void __launch_bounds__(256, 2) sgemm_kernel(
    const float* __restrict__ A, const float* __restrict__ B, float* __restrict__ C,
    int M, int N, int K, int lda, int ldb, int ldc,
    long long strideA, long long strideB, long long strideC, long long strideC2,
    int bDiv, int cDiv, float alpha)
{
    int z = blockIdx.z;
    A += (long long)z * strideA;
    B += (long long)(z / bDiv) * strideB;
    C += (long long)(z / cDiv) * strideC + (long long)(z % cDiv) * strideC2;

    const int m0 = blockIdx.y * 128;
    const int n0 = blockIdx.x * 128;
    const int t  = threadIdx.x;
    const int tx = t & 15;     // 0..15 -> 8 cols each
    const int ty = t >> 4;     // 0..15 -> 8 rows each

    if (CAUSAL && n0 > m0 + 127) {
        // fully masked tile: no compute
        #pragma unroll
        for (int i = 0; i < 8; i++)
            #pragma unroll
            for (int j = 0; j < 8; j++)
                C[(long long)(m0 + ty*8 + i) * ldc + (n0 + tx*8 + j)] = -1e30f;
        return;
    }

    __shared__ float As[16][132];
    __shared__ float Bs[16][132];

    float acc[8][8];
    #pragma unroll
    for (int i = 0; i < 8; i++)
        #pragma unroll
        for (int j = 0; j < 8; j++) acc[i][j] = 0.0f;

    int kEnd = K;
    if (CAUSAL_K) { int ke = m0 + 128; kEnd = (ke < K) ? ke : K; }

    const int arow  = t >> 1;        // 0..127
    const int ahalf = (t & 1) * 8;   // 0 or 8

    for (int k0 = 0; k0 < kEnd; k0 += 16) {
        // ---- A tile: rows m0+arow, cols k0+ahalf..+7, transposed into As[k][m]
        {
            const float* ap = A + (long long)(m0 + arow) * lda + k0 + ahalf;
            float4 a0 = *(const float4*)(ap);
            float4 a1 = *(const float4*)(ap + 4);
            As[ahalf+0][arow] = a0.x; As[ahalf+1][arow] = a0.y;
            As[ahalf+2][arow] = a0.z; As[ahalf+3][arow] = a0.w;
            As[ahalf+4][arow] = a1.x; As[ahalf+5][arow] = a1.y;
            As[ahalf+6][arow] = a1.z; As[ahalf+7][arow] = a1.w;
        }
        // ---- B tile
        if (TRANS_B) {
            const float* bp = B + (long long)(n0 + arow) * ldb + k0 + ahalf;
            float4 b0 = *(const float4*)(bp);
            float4 b1 = *(const float4*)(bp + 4);
            Bs[ahalf+0][arow] = b0.x; Bs[ahalf+1][arow] = b0.y;
            Bs[ahalf+2][arow] = b0.z; Bs[ahalf+3][arow] = b0.w;
            Bs[ahalf+4][arow] = b1.x; Bs[ahalf+5][arow] = b1.y;
            Bs[ahalf+6][arow] = b1.z; Bs[ahalf+7][arow] = b1.w;
        } else {
            #pragma unroll
            for (int r = 0; r < 2; r++) {
                int f  = t + r * 256;        // 0..511
                int kk = f >> 5;             // 0..15
                int nn = (f & 31) * 4;       // 0..124
                float4 b = *(const float4*)(B + (long long)(k0 + kk) * ldb + n0 + nn);
                *(float4*)(&Bs[kk][nn]) = b;
            }
        }
        __syncthreads();

        #pragma unroll
        for (int k = 0; k < 16; k++) {
            float ra[8], rb[8];
            #pragma unroll
            for (int i = 0; i < 8; i++) ra[i] = As[k][ty*8 + i];
            #pragma unroll
            for (int j = 0; j < 8; j++) rb[j] = Bs[k][tx*8 + j];
            #pragma unroll
            for (int i = 0; i < 8; i++)
                #pragma unroll
                for (int j = 0; j < 8; j++)
                    acc[i][j] = fmaf(ra[i], rb[j], acc[i][j]);
        }
        __syncthreads();
    }

    #pragma unroll
    for (int i = 0; i < 8; i++) {
        int gm = m0 + ty*8 + i;
        #pragma unroll
        for (int j = 0; j < 8; j++) {
            int gn = n0 + tx*8 + j;
            float v = acc[i][j] * alpha;
            if (CAUSAL && gn > gm) v = -1e30f;
            C[(long long)gm * ldc + gn] = v;
        }
    }
}

// ---------------- RMSNorm + RoPE + gain + relayout to [b,h,s,d] ----------------
// in:  [m, nHeads*128] (m = b*SEQ + s) ; out: [(b*nHeads+h)*SEQ + s, 128]
__global__ void postproc_kernel(const float* __restrict__ in, float* __restrict__ out,
                                const float* __restrict__ gain, int nHeads, int doNormRope)
{
    const int m = blockIdx.x;
    const int h = blockIdx.y;
    const int d = threadIdx.x;       // 0..127
    const int b = m / SEQ, s = m % SEQ;

    float v = in[(long long)m * (nHeads * HD) + h * HD + d];

    __shared__ float red[128];
    __shared__ float vec[128];

    if (doNormRope) {
        red[d] = v * v;
        __syncthreads();
        #pragma unroll
        for (int off = 64; off > 0; off >>= 1) {
            if (d < off) red[d] += red[d + off];
            __syncthreads();
        }
        float ms = red[0] * (1.0f / 128.0f);
        v = v * rsqrtf(ms + EPSV);
        vec[d] = v;
        __syncthreads();
        if (d < ROPE) {
            int j = d & 31;
            float inv_freq = powf(10000.0f, -(float)j / 32.0f);
            float ang = (float)s * inv_freq;
            float c = cosf(ang), sn = sinf(ang);
            float x1 = vec[j], x2 = vec[j + 32];
            v = (d < 32) ? (x1 * c + x2 * sn) : (-x1 * sn + x2 * c);
        }
    }
    if (gain) v *= gain[h];

    out[((long long)(b * nHeads + h) * SEQ + s) * HD + d] = v;
}

// ---------------- row softmax (row length 2048, in place) ----------------
__global__ void softmax_kernel(float* __restrict__ S)
{
    float* p = S + (long long)blockIdx.x * SEQ;
    const int t = threadIdx.x;   // 256
    float v[8];
    float m = -3.4e38f;
    #pragma unroll
    for (int i = 0; i < 8; i++) { v[i] = p[t + i * 256]; m = fmaxf(m, v[i]); }

    __shared__ float red[256];
    red[t] = m; __syncthreads();
    #pragma unroll
    for (int off = 128; off > 0; off >>= 1) {
        if (t < off) red[t] = fmaxf(red[t], red[t + off]);
        __syncthreads();
    }
    m = red[0];
    __syncthreads();

    float s = 0.0f;
    #pragma unroll
    for (int i = 0; i < 8; i++) { v[i] = expf(v[i] - m); s += v[i]; }
    red[t] = s; __syncthreads();
    #pragma unroll
    for (int off = 128; off > 0; off >>= 1) {
        if (t < off) red[t] += red[t + off];
        __syncthreads();
    }
    float inv = 1.0f / red[0];
    #pragma unroll
    for (int i = 0; i < 8; i++) p[t + i * 256] = v[i] * inv;
}

// ---------------- launch ----------------
extern "C" void kernel_launch(void* const* d_in, const int* in_sizes, int n_in,
                              void* d_out, int out_size)
{
    const float* x     = (const float*)d_in[0];
    const float* q_w   = (const float*)d_in[1];
    const float* k_w   = (const float*)d_in[2];
    const float* v_w   = (const float*)d_in[3];
    const float* out_w = (const float*)d_in[4];
    const float* q_g   = (const float*)d_in[5];
    float* out = (float*)d_out;

    static float *Qb=nullptr,*Kb=nullptr,*Vb=nullptr,*Qp=nullptr,*Kp=nullptr,*Vp=nullptr,*Sb=nullptr,*Yb=nullptr;
    if (!Qb) {
        cudaGetSymbolAddress((void**)&Qb, g_Qb);
        cudaGetSymbolAddress((void**)&Kb, g_Kb);
        cudaGetSymbolAddress((void**)&Vb, g_Vb);
        cudaGetSymbolAddress((void**)&Qp, g_Qp);
        cudaGetSymbolAddress((void**)&Kp, g_Kp);
        cudaGetSymbolAddress((void**)&Vp, g_Vp);
        cudaGetSymbolAddress((void**)&Sb, g_S);
        cudaGetSymbolAddress((void**)&Yb, g_Y);
    }

    const long long SS = (long long)SEQ * SEQ;
    const long long SH = (long long)SEQ * HD;

    // 1-3) QKV projections: C = X @ W^T
    sgemm_kernel<true,false,false><<<dim3(DMODEL/128, MTOK/128, 1), 256>>>(
        x, q_w, Qb, MTOK, DMODEL, DMODEL, DMODEL, DMODEL, DMODEL, 0,0,0,0, 1,1, 1.0f);
    sgemm_kernel<true,false,false><<<dim3((NKV*HD)/128, MTOK/128, 1), 256>>>(
        x, k_w, Kb, MTOK, NKV*HD, DMODEL, DMODEL, DMODEL, NKV*HD, 0,0,0,0, 1,1, 1.0f);
    sgemm_kernel<true,false,false><<<dim3((NKV*HD)/128, MTOK/128, 1), 256>>>(
        x, v_w, Vb, MTOK, NKV*HD, DMODEL, DMODEL, DMODEL, NKV*HD, 0,0,0,0, 1,1, 1.0f);

    // 4-6) norm/rope/gain + relayout
    postproc_kernel<<<dim3(MTOK, NH),  128>>>(Qb, Qp, q_g,     NH,  1);
    postproc_kernel<<<dim3(MTOK, NKV), 128>>>(Kb, Kp, nullptr, NKV, 1);
    postproc_kernel<<<dim3(MTOK, NKV), 128>>>(Vb, Vp, nullptr, NKV, 0);

    // 7) scores = Qp @ Kp^T * scale, causal mask. z = b*16+h, kv batch = z/4
    sgemm_kernel<true,true,false><<<dim3(SEQ/128, SEQ/128, BATCH*NH), 256>>>(
        Qp, Kp, Sb, SEQ, SEQ, HD, HD, HD, SEQ,
        SH, SH, SS, 0, /*bDiv=*/4, /*cDiv=*/1, 0.08838834764831845f);

    // 8) softmax rows
    softmax_kernel<<<BATCH*NH*SEQ, 256>>>(Sb);

    // 9) Y = P @ V   (NN, causal K-bound). C goes to [b, s, h*128+d]:
    //    offset = (z/16)*SEQ*2048 + (z%16)*128
    sgemm_kernel<false,false,true><<<dim3(HD/128, SEQ/128, BATCH*NH), 256>>>(
        Sb, Vp, Yb, SEQ, HD, SEQ, SEQ, HD, DMODEL,
        SS, SH, (long long)SEQ*DMODEL, HD, /*bDiv=*/4, /*cDiv=*/NH, 1.0f);

    // 10) out = Y @ out_w^T
    sgemm_kernel<true,false,false><<<dim3(DMODEL/128, MTOK/128, 1), 256>>>(
        Yb, out_w, out, MTOK, DMODEL, DMODEL, DMODEL, DMODEL, DMODEL, 0,0,0,0, 1,1, 1.0f);
}

// round 2
// speedup vs baseline: 1.0471x; 1.0471x over previous
#include <cuda_runtime.h>
#include <cuda_bf16.h>
#include <math.h>

// Problem constants
#define BATCH 2
#define SEQ   2048
#define DMODEL 2048
#define NH    16
#define NKV   4
#define HD    128
#define ROPE  64
#define MTOK  (BATCH*SEQ)          // 4096 tokens
#define EPSV  1.1920929e-07f

// ---------------- scratch (device globals; allocation-free) ----------------
__device__ float g_Qb[(long long)MTOK * DMODEL];          // 32 MB
__device__ float g_Kb[(long long)MTOK * (NKV*HD)];        // 8 MB
__device__ float g_Vb[(long long)MTOK * (NKV*HD)];        // 8 MB
__device__ float g_Qp[(long long)BATCH*NH  * SEQ * HD];   // 32 MB
__device__ float g_Kp[(long long)BATCH*NKV * SEQ * HD];   // 8 MB
__device__ float g_Vp[(long long)BATCH*NKV * SEQ * HD];   // 8 MB
__device__ float g_S [(long long)BATCH*NH  * SEQ * SEQ];  // 537 MB
__device__ float g_Y [(long long)MTOK * DMODEL];          // 32 MB

#define FFMA2(d, a, b) asm("fma.rn.f32x2 %0, %1, %2, %0;" : "+l"(d) : "l"(a), "l"(b))
#define SPLAT2(d, f)   asm("mov.b64 %0, {%1, %1};" : "=l"(d) : "f"(f))

// ---------------- 128x128 register-tiled SGEMM with packed f32x2 FMA ----------------
// C[m,n] = alpha * sum_k A[m,k] * B(k,n)     (B(k,n)=B[n,k] if TRANS_B)
// CAUSAL: skip fully masked tiles entirely (no stores!); mask partial tiles with -1e30.
// CAUSAL_K: bound K loop at m0+128.
template<bool TRANS_B, bool CAUSAL, bool CAUSAL_K>
__global__ void __launch_bounds__(256, 2) sgemm_kernel(
    const float* __restrict__ A, const float* __restrict__ B, float* __restrict__ C,
    int M, int N, int K, int lda, int ldb, int ldc,
    long long strideA, long long strideB, long long strideC, long long strideC2,
    int bDiv, int cDiv, float alpha)
{
    int z = blockIdx.z;
    A += (long long)z * strideA;
    B += (long long)(z / bDiv) * strideB;
    C += (long long)(z / cDiv) * strideC + (long long)(z % cDiv) * strideC2;

    const int m0 = blockIdx.y * 128;
    const int n0 = blockIdx.x * 128;
    const int t  = threadIdx.x;
    const int tx = t & 15;     // 0..15 -> 8 cols each
    const int ty = t >> 4;     // 0..15 -> 8 rows each

    if (CAUSAL && n0 > m0 + 127) return;   // fully masked: write nothing

    __shared__ float As[16][132];
    __shared__ float Bs[16][132];

    // 8 rows x 4 packed col-pairs of fp32x2 accumulators
    unsigned long long acc[8][4];
    #pragma unroll
    for (int i = 0; i < 8; i++)
        #pragma unroll
        for (int j = 0; j < 4; j++) acc[i][j] = 0ULL;

    int kEnd = K;
    if (CAUSAL_K) { int ke = m0 + 128; kEnd = (ke < K) ? ke : K; }

    const int arow  = t >> 1;        // 0..127
    const int ahalf = (t & 1) * 8;   // 0 or 8

    for (int k0 = 0; k0 < kEnd; k0 += 16) {
        {
            const float* ap = A + (long long)(m0 + arow) * lda + k0 + ahalf;
            float4 a0 = *(const float4*)(ap);
            float4 a1 = *(const float4*)(ap + 4);
            As[ahalf+0][arow] = a0.x; As[ahalf+1][arow] = a0.y;
            As[ahalf+2][arow] = a0.z; As[ahalf+3][arow] = a0.w;
            As[ahalf+4][arow] = a1.x; As[ahalf+5][arow] = a1.y;
            As[ahalf+6][arow] = a1.z; As[ahalf+7][arow] = a1.w;
        }
        if (TRANS_B) {
            const float* bp = B + (long long)(n0 + arow) * ldb + k0 + ahalf;
            float4 b0 = *(const float4*)(bp);
            float4 b1 = *(const float4*)(bp + 4);
            Bs[ahalf+0][arow] = b0.x; Bs[ahalf+1][arow] = b0.y;
            Bs[ahalf+2][arow] = b0.z; Bs[ahalf+3][arow] = b0.w;
            Bs[ahalf+4][arow] = b1.x; Bs[ahalf+5][arow] = b1.y;
            Bs[ahalf+6][arow] = b1.z; Bs[ahalf+7][arow] = b1.w;
        } else {
            #pragma unroll
            for (int r = 0; r < 2; r++) {
                int f  = t + r * 256;
                int kk = f >> 5;
                int nn = (f & 31) * 4;
                float4 b = *(const float4*)(B + (long long)(k0 + kk) * ldb + n0 + nn);
                *(float4*)(&Bs[kk][nn]) = b;
            }
        }
        __syncthreads();

        #pragma unroll
        for (int k = 0; k < 16; k++) {
            // rb: 4 packed pairs (8B-aligned: col offset tx*8+2j is even, row
            // stride 132*4=528 bytes is 16B-aligned)
            unsigned long long rb[4];
            #pragma unroll
            for (int j = 0; j < 4; j++)
                rb[j] = *(const unsigned long long*)(&Bs[k][tx*8 + 2*j]);
            unsigned long long ra[8];
            #pragma unroll
            for (int i = 0; i < 8; i++) { float a = As[k][ty*8 + i]; SPLAT2(ra[i], a); }
            #pragma unroll
            for (int i = 0; i < 8; i++)
                #pragma unroll
                for (int j = 0; j < 4; j++)
                    FFMA2(acc[i][j], ra[i], rb[j]);
        }
        __syncthreads();
    }

    #pragma unroll
    for (int i = 0; i < 8; i++) {
        int gm = m0 + ty*8 + i;
        #pragma unroll
        for (int j = 0; j < 4; j++) {
            uint2 u = *(uint2*)&acc[i][j];
            float v0 = __uint_as_float(u.x) * alpha;
            float v1 = __uint_as_float(u.y) * alpha;
            int gn = n0 + tx*8 + 2*j;
            if (CAUSAL) {
                if (gn     > gm) v0 = -1e30f;
                if (gn + 1 > gm) v1 = -1e30f;
            }
            C[(long long)gm * ldc + gn]     = v0;
            C[(long long)gm * ldc + gn + 1] = v1;
        }
    }
}

// ---------------- RMSNorm + RoPE + gain + relayout to [b,h,s,d] ----------------
__global__ void postproc_kernel(const float* __restrict__ in, float* __restrict__ out,
                                const float* __restrict__ gain, int nHeads, int doNormRope)
{
    const int m = blockIdx.x;
    const int h = blockIdx.y;
    const int d = threadIdx.x;       // 0..127
    const int b = m / SEQ, s = m % SEQ;

    float v = in[(long long)m * (nHeads * HD) + h * HD + d];

    __shared__ float red[128];
    __shared__ float vec[128];

    if (doNormRope) {
        red[d] = v * v;
        __syncthreads();
        #pragma unroll
        for (int off = 64; off > 0; off >>= 1) {
            if (d < off) red[d] += red[d + off];
            __syncthreads();
        }
        float ms = red[0] * (1.0f / 128.0f);
        v = v * rsqrtf(ms + EPSV);
        vec[d] = v;
        __syncthreads();
        if (d < ROPE) {
            int j = d & 31;
            float inv_freq = powf(10000.0f, -(float)j / 32.0f);
            float ang = (float)s * inv_freq;
            float c = cosf(ang), sn = sinf(ang);
            float x1 = vec[j], x2 = vec[j + 32];
            v = (d < 32) ? (x1 * c + x2 * sn) : (-x1 * sn + x2 * c);
        }
    }
    if (gain) v *= gain[h];

    out[((long long)(b * nHeads + h) * SEQ + s) * HD + d] = v;
}

// ---------------- causal row softmax (row length 2048, in place) ----------------
// Row r (within head) has valid columns [0, r]. Masked score tiles were never
// written, so: load only j <= r (else -inf), store zeros out to the row's
// 128-aligned tile end (exactly the region the causal-bounded PV GEMM reads).
__global__ void softmax_kernel(float* __restrict__ S)
{
    const int r = blockIdx.x % SEQ;                 // row within head
    float* p = S + (long long)blockIdx.x * SEQ;
    const int t = threadIdx.x;   // 256
    const int tileEnd = ((r >> 7) + 1) << 7;        // store bound

    float v[8];
    float m = -3.4e38f;
    #pragma unroll
    for (int i = 0; i < 8; i++) {
        int j = t + i * 256;
        v[i] = (j <= r) ? p[j] : -3.4e38f;
        m = fmaxf(m, v[i]);
    }

    __shared__ float red[256];
    red[t] = m; __syncthreads();
    #pragma unroll
    for (int off = 128; off > 0; off >>= 1) {
        if (t < off) red[t] = fmaxf(red[t], red[t + off]);
        __syncthreads();
    }
    m = red[0];
    __syncthreads();

    float s = 0.0f;
    #pragma unroll
    for (int i = 0; i < 8; i++) { v[i] = expf(v[i] - m); s += v[i]; }
    red[t] = s; __syncthreads();
    #pragma unroll
    for (int off = 128; off > 0; off >>= 1) {
        if (t < off) red[t] += red[t + off];
        __syncthreads();
    }
    float inv = 1.0f / red[0];
    #pragma unroll
    for (int i = 0; i < 8; i++) {
        int j = t + i * 256;
        if (j < tileEnd) p[j] = v[i] * inv;
    }
}

// ---------------- launch ----------------
extern "C" void kernel_launch(void* const* d_in, const int* in_sizes, int n_in,
                              void* d_out, int out_size)
{
    const float* x     = (const float*)d_in[0];
    const float* q_w   = (const float*)d_in[1];
    const float* k_w   = (const float*)d_in[2];
    const float* v_w   = (const float*)d_in[3];
    const float* out_w = (const float*)d_in[4];
    const float* q_g   = (const float*)d_in[5];
    float* out = (float*)d_out;

    static float *Qb=nullptr,*Kb=nullptr,*Vb=nullptr,*Qp=nullptr,*Kp=nullptr,*Vp=nullptr,*Sb=nullptr,*Yb=nullptr;
    if (!Qb) {
        cudaGetSymbolAddress((void**)&Qb, g_Qb);
        cudaGetSymbolAddress((void**)&Kb, g_Kb);
        cudaGetSymbolAddress((void**)&Vb, g_Vb);
        cudaGetSymbolAddress((void**)&Qp, g_Qp);
        cudaGetSymbolAddress((void**)&Kp, g_Kp);
        cudaGetSymbolAddress((void**)&Vp, g_Vp);
        cudaGetSymbolAddress((void**)&Sb, g_S);
        cudaGetSymbolAddress((void**)&Yb, g_Y);
    }

    const long long SS = (long long)SEQ * SEQ;
    const long long SH = (long long)SEQ * HD;

    // 1-3) QKV projections: C = X @ W^T
    sgemm_kernel<true,false,false><<<dim3(DMODEL/128, MTOK/128, 1), 256>>>(
        x, q_w, Qb, MTOK, DMODEL, DMODEL, DMODEL, DMODEL, DMODEL, 0,0,0,0, 1,1, 1.0f);
    sgemm_kernel<true,false,false><<<dim3((NKV*HD)/128, MTOK/128, 1), 256>>>(
        x, k_w, Kb, MTOK, NKV*HD, DMODEL, DMODEL, DMODEL, NKV*HD, 0,0,0,0, 1,1, 1.0f);
    sgemm_kernel<true,false,false><<<dim3((NKV*HD)/128, MTOK/128, 1), 256>>>(
        x, v_w, Vb, MTOK, NKV*HD, DMODEL, DMODEL, DMODEL, NKV*HD, 0,0,0,0, 1,1, 1.0f);

    // 4-6) norm/rope/gain + relayout
    postproc_kernel<<<dim3(MTOK, NH),  128>>>(Qb, Qp, q_g,     NH,  1);
    postproc_kernel<<<dim3(MTOK, NKV), 128>>>(Kb, Kp, nullptr, NKV, 1);
    postproc_kernel<<<dim3(MTOK, NKV), 128>>>(Vb, Vp, nullptr, NKV, 0);

    // 7) scores = Qp @ Kp^T * scale, causal (masked tiles untouched)
    sgemm_kernel<true,true,false><<<dim3(SEQ/128, SEQ/128, BATCH*NH), 256>>>(
        Qp, Kp, Sb, SEQ, SEQ, HD, HD, HD, SEQ,
        SH, SH, SS, 0, /*bDiv=*/4, /*cDiv=*/1, 0.08838834764831845f);

    // 8) causal softmax rows
    softmax_kernel<<<BATCH*NH*SEQ, 256>>>(Sb);

    // 9) Y = P @ V   (NN, causal K-bound), into [b, s, h*128+d]
    sgemm_kernel<false,false,true><<<dim3(HD/128, SEQ/128, BATCH*NH), 256>>>(
        Sb, Vp, Yb, SEQ, HD, SEQ, SEQ, HD, DMODEL,
        SS, SH, (long long)SEQ*DMODEL, HD, /*bDiv=*/4, /*cDiv=*/NH, 1.0f);

    // 10) out = Y @ out_w^T
    sgemm_kernel<true,false,false><<<dim3(DMODEL/128, MTOK/128, 1), 256>>>(
        Yb, out_w, out, MTOK, DMODEL, DMODEL, DMODEL, DMODEL, DMODEL, 0,0,0,0, 1,1, 1.0f);
}

// round 5
// speedup vs baseline: 1.8322x; 1.7497x over previous
#include <cuda_runtime.h>
#include <cuda_bf16.h>
#include <cstdint>
#include <math.h>

#define BATCH 2
#define SEQ   2048
#define DMODEL 2048
#define NH    16
#define NKV   4
#define HD    128
#define ROPE  64
#define MTOK  (BATCH*SEQ)
#define EPSV  1.1920929e-07f

typedef __nv_bfloat16 bf16;

// ---------------- scratch (triple-interleaved hi/lo bf16 along K) ----------------
// A-side pattern per element: (hi, lo, hi). B-side pattern: (hi, hi, lo).
__device__ bf16 g_x3 [(size_t)MTOK*3*DMODEL];        // 48 MB  (A-side)
__device__ bf16 g_qw3[(size_t)DMODEL*3*DMODEL];      // 24 MB  (B-side)
__device__ bf16 g_kw3[(size_t)NKV*HD*3*DMODEL];      // 6 MB   (B-side)
__device__ bf16 g_vw3[(size_t)NKV*HD*3*DMODEL];      // 6 MB   (B-side)
__device__ bf16 g_ow3[(size_t)DMODEL*3*DMODEL];      // 24 MB  (B-side)
__device__ float g_Qb[(size_t)MTOK*DMODEL];          // 32 MB
__device__ float g_Kb[(size_t)MTOK*NKV*HD];          // 8 MB
__device__ float g_Vb[(size_t)MTOK*NKV*HD];          // 8 MB
__device__ bf16 g_Qp3[(size_t)BATCH*NH*SEQ*3*HD];    // 48 MB  (A-side)
__device__ bf16 g_Kp3[(size_t)BATCH*NKV*SEQ*3*HD];   // 12 MB  (B-side)
__device__ bf16 g_Vt3[(size_t)BATCH*NKV*HD*3*SEQ];   // 12 MB  (B-side)
__device__ float g_S [(size_t)BATCH*NH*SEQ*SEQ];     // 537 MB
__device__ bf16 g_P3 [(size_t)BATCH*NH*SEQ*3*SEQ];   // 805 MB (A-side)
__device__ bf16 g_Y3 [(size_t)MTOK*3*DMODEL];        // 48 MB  (A-side)

__device__ __forceinline__ void split2(float v, bf16& h, bf16& l) {
    h = __float2bfloat16_rn(v);
    l = __float2bfloat16_rn(v - __bfloat162float(h));
}
__device__ __forceinline__ uint32_t pk(bf16 a, bf16 b) {
    return (uint32_t)__bfloat16_as_ushort(a) | ((uint32_t)__bfloat16_as_ushort(b) << 16);
}

// ---------------- PTX helpers (baseline PTX only) ----------------
__device__ __forceinline__ uint32_t smem_u32(const void* p) {
    uint32_t a;
    asm("{ .reg .u64 t; cvta.to.shared.u64 t, %1; cvt.u32.u64 %0, t; }" : "=r"(a) : "l"(p));
    return a;
}
__device__ __forceinline__ void ldsm4(uint32_t* r, uint32_t addr) {
    asm volatile("ldmatrix.sync.aligned.m8n8.x4.shared.b16 {%0,%1,%2,%3}, [%4];"
                 : "=r"(r[0]), "=r"(r[1]), "=r"(r[2]), "=r"(r[3]) : "r"(addr));
}
__device__ __forceinline__ void mma16816(float* c, const uint32_t* a, const uint32_t* b) {
    asm volatile(
        "mma.sync.aligned.m16n8k16.row.col.f32.bf16.bf16.f32 "
        "{%0,%1,%2,%3}, {%4,%5,%6,%7}, {%8,%9}, {%0,%1,%2,%3};"
        : "+f"(c[0]), "+f"(c[1]), "+f"(c[2]), "+f"(c[3])
        : "r"(a[0]), "r"(a[1]), "r"(a[2]), "r"(a[3]), "r"(b[0]), "r"(b[1]));
}
#define CP_ASYNC16(dst, src) \
    asm volatile("cp.async.cg.shared.global [%0], [%1], 16;" :: "r"(dst), "l"(src) : "memory")
#define CP_COMMIT() asm volatile("cp.async.commit_group;" ::: "memory")
#define CP_WAIT(n)  asm volatile("cp.async.wait_group %0;" :: "n"(n) : "memory")

// ---------------- bf16 mma GEMM over interleaved K3 ----------------
// C[m,n] = alpha * sum_{k3} A[m,k3]*B[n,k3].  Tiles 128x128x32, 8 warps.
#define PADK 40
#define TILEB (128*PADK*2)

template<bool CAUSAL, bool CAUSAL_K, bool BF16_OUT>
__global__ void __launch_bounds__(256, 2) mm_kernel(
    const bf16* __restrict__ A, const bf16* __restrict__ B,
    float* __restrict__ C, bf16* __restrict__ C3,
    int K3, int lda, int ldb, int ldc,
    long long sA, long long sB, long long sC, long long sC2,
    int bDiv, int cDiv, float alpha)
{
    const int z = blockIdx.z;
    A += (long long)z * sA;
    B += (long long)(z / bDiv) * sB;
    const long long cOff = (long long)(z / cDiv) * sC + (long long)(z % cDiv) * sC2;

    const int m0 = blockIdx.y * 128;
    const int n0 = blockIdx.x * 128;
    if (CAUSAL && n0 > m0 + 127) return;

    __shared__ bf16 shA[2][128 * PADK];
    __shared__ bf16 shB[2][128 * PADK];
    const uint32_t sAaddr = smem_u32(shA);
    const uint32_t sBaddr = smem_u32(shB);

    const int t = threadIdx.x;
    const int w = t >> 5, lane = t & 31;
    const int wr = w >> 2, wc = w & 3;          // 2x4 warp grid
    const int mBase = wr * 64, nBase = wc * 32;

    const int aRow = mBase + (lane & 7) + ((lane >> 3) & 1) * 8;
    const int aK   = (lane >> 4) * 8;
    const int bRow = nBase + (lane & 7) + ((lane >> 4) & 1) * 8;
    const int bK   = ((lane >> 3) & 1) * 8;

    const int lr = t >> 1;
    const int lc = (t & 1) * 2;

    int kEnd = K3;
    if (CAUSAL_K) { int ke = 3 * (m0 + 128); kEnd = (ke < K3) ? ke : K3; }
    const int nc = kEnd >> 5;

    const bf16* gA = A + (long long)(m0 + lr) * lda + lc * 8;
    const bf16* gB = B + (long long)(n0 + lr) * ldb + lc * 8;
    const uint32_t dA = sAaddr + (lr * PADK + lc * 8) * 2;
    const uint32_t dB = sBaddr + (lr * PADK + lc * 8) * 2;

    float acc[4][4][4];
    #pragma unroll
    for (int i = 0; i < 4; i++)
        #pragma unroll
        for (int j = 0; j < 4; j++)
            #pragma unroll
            for (int q = 0; q < 4; q++) acc[i][j][q] = 0.0f;

    CP_ASYNC16(dA, gA);           CP_ASYNC16(dA + 16, gA + 8);
    CP_ASYNC16(dB, gB);           CP_ASYNC16(dB + 16, gB + 8);
    CP_COMMIT();

    for (int i = 0; i < nc; i++) {
        if (i + 1 < nc) {
            const int nb = (i + 1) & 1;
            const bf16* pA = gA + (i + 1) * 32;
            const bf16* pB = gB + (i + 1) * 32;
            CP_ASYNC16(dA + nb * TILEB, pA);      CP_ASYNC16(dA + nb * TILEB + 16, pA + 8);
            CP_ASYNC16(dB + nb * TILEB, pB);      CP_ASYNC16(dB + nb * TILEB + 16, pB + 8);
            CP_COMMIT();
            CP_WAIT(1);
        } else {
            CP_WAIT(0);
        }
        __syncthreads();

        const uint32_t ab = sAaddr + (i & 1) * TILEB;
        const uint32_t bb = sBaddr + (i & 1) * TILEB;
        #pragma unroll
        for (int ks = 0; ks < 2; ks++) {
            uint32_t af[4][4], bfr[2][4];
            #pragma unroll
            for (int fm = 0; fm < 4; fm++)
                ldsm4(af[fm], ab + ((aRow + fm * 16) * PADK + ks * 16 + aK) * 2);
            #pragma unroll
            for (int bg = 0; bg < 2; bg++)
                ldsm4(bfr[bg], bb + ((bRow + bg * 16) * PADK + ks * 16 + bK) * 2);
            #pragma unroll
            for (int fm = 0; fm < 4; fm++)
                #pragma unroll
                for (int fn = 0; fn < 4; fn++)
                    mma16816(acc[fm][fn], af[fm], &bfr[fn >> 1][(fn & 1) * 2]);
        }
        __syncthreads();
    }

    const int g = lane >> 2, tg = lane & 3;
    #pragma unroll
    for (int fm = 0; fm < 4; fm++) {
        #pragma unroll
        for (int fn = 0; fn < 4; fn++) {
            const int col = n0 + nBase + fn * 8 + tg * 2;
            #pragma unroll
            for (int half = 0; half < 2; half++) {
                const int row = m0 + mBase + fm * 16 + g + half * 8;
                float v0 = acc[fm][fn][half * 2]     * alpha;
                float v1 = acc[fm][fn][half * 2 + 1] * alpha;
                if (BF16_OUT) {
                    // A-side triple: (hi, lo, hi) for col and col+1 -> 6 bf16 = 3 u32
                    bf16 h0, l0, h1, l1;
                    split2(v0, h0, l0); split2(v1, h1, l1);
                    uint32_t* dst = reinterpret_cast<uint32_t*>(
                        C3 + cOff + (long long)row * ldc + 3 * col);
                    dst[0] = pk(h0, l0);
                    dst[1] = pk(h0, h1);
                    dst[2] = pk(l1, h1);
                } else {
                    if (CAUSAL) {
                        if (col     > row) v0 = -1e30f;
                        if (col + 1 > row) v1 = -1e30f;
                    }
                    float2 f; f.x = v0; f.y = v1;
                    *reinterpret_cast<float2*>(C + cOff + (long long)row * ldc + col) = f;
                }
            }
        }
    }
}

// ---------------- fp32 -> triple-interleaved bf16 ----------------
// ASIDE: (hi, lo, hi)  |  !ASIDE: (hi, hi, lo).  Each thread: 4 floats -> 12 bf16 (24 B).
template<bool ASIDE>
__global__ void split3_kernel(const float* __restrict__ in, bf16* __restrict__ o3, long long n4)
{
    long long i = (long long)blockIdx.x * blockDim.x + threadIdx.x;
    if (i >= n4) return;
    float4 v = reinterpret_cast<const float4*>(in)[i];
    bf16 h[4], l[4];
    split2(v.x, h[0], l[0]); split2(v.y, h[1], l[1]);
    split2(v.z, h[2], l[2]); split2(v.w, h[3], l[3]);
    uint32_t u[6];
    if (ASIDE) {
        u[0] = pk(h[0], l[0]); u[1] = pk(h[0], h[1]); u[2] = pk(l[1], h[1]);
        u[3] = pk(h[2], l[2]); u[4] = pk(h[2], h[3]); u[5] = pk(l[3], h[3]);
    } else {
        u[0] = pk(h[0], h[0]); u[1] = pk(l[0], h[1]); u[2] = pk(h[1], l[1]);
        u[3] = pk(h[2], h[2]); u[4] = pk(l[2], h[3]); u[5] = pk(h[3], l[3]);
    }
    uint2* dst = reinterpret_cast<uint2*>(o3 + i * 12);
    dst[0] = make_uint2(u[0], u[1]);
    dst[1] = make_uint2(u[2], u[3]);
    dst[2] = make_uint2(u[4], u[5]);
}

// ---------------- RMSNorm + RoPE + gain -> triple bf16 [b,h,s,3d] ----------------
template<bool ASIDE>
__global__ void postproc_qk(const float* __restrict__ in, bf16* __restrict__ o3,
                            const float* __restrict__ gain, int nHeads)
{
    const int m = blockIdx.x, h = blockIdx.y, d = threadIdx.x;
    const int b = m / SEQ, s = m % SEQ;
    float v = in[(long long)m * (nHeads * HD) + h * HD + d];

    __shared__ float red[128];
    __shared__ float vec[128];
    red[d] = v * v;
    __syncthreads();
    #pragma unroll
    for (int off = 64; off > 0; off >>= 1) {
        if (d < off) red[d] += red[d + off];
        __syncthreads();
    }
    float ms = red[0] * (1.0f / 128.0f);
    v = v * rsqrtf(ms + EPSV);
    vec[d] = v;
    __syncthreads();
    if (d < ROPE) {
        int j = d & 31;
        float inv_freq = powf(10000.0f, -(float)j / 32.0f);
        float ang = (float)s * inv_freq;
        float c = cosf(ang), sn = sinf(ang);
        float x1 = vec[j], x2 = vec[j + 32];
        v = (d < 32) ? (x1 * c + x2 * sn) : (-x1 * sn + x2 * c);
    }
    if (gain) v *= gain[h];

    bf16 hh, ll; split2(v, hh, ll);
    bf16* o = o3 + ((long long)(b * nHeads + h) * SEQ + s) * (3 * HD) + 3 * d;
    if (ASIDE) { o[0] = hh; o[1] = ll; o[2] = hh; }
    else       { o[0] = hh; o[1] = hh; o[2] = ll; }
}

// ---------------- V: split + transpose to [b,kv,d,3s] (B-side) ----------------
__global__ void transpose_v(const float* __restrict__ in, bf16* __restrict__ o3)
{
    const int m = blockIdx.x, h = blockIdx.y, d = threadIdx.x;
    const int b = m / SEQ, s = m % SEQ;
    float v = in[(long long)m * (NKV * HD) + h * HD + d];
    bf16 hh, ll; split2(v, hh, ll);
    bf16* o = o3 + ((long long)(b * NKV + h) * HD + d) * (3 * SEQ) + 3 * s;
    o[0] = hh; o[1] = hh; o[2] = ll;
}

// ---------------- causal softmax: fp32 S -> triple bf16 P3 (A-side) ----------------
__global__ void softmax_kernel(const float* __restrict__ S, bf16* __restrict__ P3)
{
    const int r = blockIdx.x % SEQ;
    const float* p = S + (long long)blockIdx.x * SEQ;
    bf16* q3 = P3 + (long long)blockIdx.x * (3 * SEQ);
    const int t = threadIdx.x;
    const int tileEnd = ((r >> 7) + 1) << 7;

    float v[8];
    float m = -3.4e38f;
    #pragma unroll
    for (int i = 0; i < 8; i++) {
        int j = t + i * 256;
        v[i] = (j <= r) ? p[j] : -3.4e38f;
        m = fmaxf(m, v[i]);
    }
    __shared__ float red[256];
    red[t] = m; __syncthreads();
    #pragma unroll
    for (int off = 128; off > 0; off >>= 1) {
        if (t < off) red[t] = fmaxf(red[t], red[t + off]);
        __syncthreads();
    }
    m = red[0];
    __syncthreads();
    float s = 0.0f;
    #pragma unroll
    for (int i = 0; i < 8; i++) { v[i] = expf(v[i] - m); s += v[i]; }
    red[t] = s; __syncthreads();
    #pragma unroll
    for (int off = 128; off > 0; off >>= 1) {
        if (t < off) red[t] += red[t + off];
        __syncthreads();
    }
    const float inv = 1.0f / red[0];
    #pragma unroll
    for (int i = 0; i < 8; i++) {
        int j = t + i * 256;
        if (j < tileEnd) {
            bf16 hh, ll; split2(v[i] * inv, hh, ll);
            bf16* o = q3 + 3 * j;
            o[0] = hh; o[1] = ll; o[2] = hh;
        }
    }
}

// ---------------- launch ----------------
extern "C" void kernel_launch(void* const* d_in, const int* in_sizes, int n_in,
                              void* d_out, int out_size)
{
    const float* x     = (const float*)d_in[0];
    const float* q_w   = (const float*)d_in[1];
    const float* k_w   = (const float*)d_in[2];
    const float* v_w   = (const float*)d_in[3];
    const float* out_w = (const float*)d_in[4];
    const float* q_g   = (const float*)d_in[5];
    float* out = (float*)d_out;

    static bool init = false;
    static bf16 *x3,*qw3,*kw3,*vw3,*ow3,*Qp3,*Kp3,*Vt3,*P3,*Y3;
    static float *Qb,*Kb,*Vb,*Sb;
    if (!init) {
        cudaGetSymbolAddress((void**)&x3,  g_x3);
        cudaGetSymbolAddress((void**)&qw3, g_qw3);
        cudaGetSymbolAddress((void**)&kw3, g_kw3);
        cudaGetSymbolAddress((void**)&vw3, g_vw3);
        cudaGetSymbolAddress((void**)&ow3, g_ow3);
        cudaGetSymbolAddress((void**)&Qb,  g_Qb);
        cudaGetSymbolAddress((void**)&Kb,  g_Kb);
        cudaGetSymbolAddress((void**)&Vb,  g_Vb);
        cudaGetSymbolAddress((void**)&Qp3, g_Qp3);
        cudaGetSymbolAddress((void**)&Kp3, g_Kp3);
        cudaGetSymbolAddress((void**)&Vt3, g_Vt3);
        cudaGetSymbolAddress((void**)&Sb,  g_S);
        cudaGetSymbolAddress((void**)&P3,  g_P3);
        cudaGetSymbolAddress((void**)&Y3,  g_Y3);
        init = true;
    }

    const long long SS = (long long)SEQ * SEQ;
    const float scale = 0.08838834764831845f;

    // splits: x is A-side; weights are B-side
    {
        long long n4;
        n4 = (long long)MTOK * DMODEL / 4;   split3_kernel<true ><<<(unsigned)((n4+255)/256),256>>>(x, x3, n4);
        n4 = (long long)DMODEL * DMODEL / 4; split3_kernel<false><<<(unsigned)((n4+255)/256),256>>>(q_w, qw3, n4);
        n4 = (long long)NKV*HD * DMODEL / 4; split3_kernel<false><<<(unsigned)((n4+255)/256),256>>>(k_w, kw3, n4);
        n4 = (long long)NKV*HD * DMODEL / 4; split3_kernel<false><<<(unsigned)((n4+255)/256),256>>>(v_w, vw3, n4);
        n4 = (long long)DMODEL * DMODEL / 4; split3_kernel<false><<<(unsigned)((n4+255)/256),256>>>(out_w, ow3, n4);
    }

    // QKV projections (fp32 out), K3 = 3*DMODEL = 6144
    mm_kernel<false,false,false><<<dim3(DMODEL/128, MTOK/128, 1), 256>>>(
        x3, qw3, Qb, nullptr, 3*DMODEL, 3*DMODEL, 3*DMODEL, DMODEL, 0,0,0,0, 1,1, 1.0f);
    mm_kernel<false,false,false><<<dim3((NKV*HD)/128, MTOK/128, 1), 256>>>(
        x3, kw3, Kb, nullptr, 3*DMODEL, 3*DMODEL, 3*DMODEL, NKV*HD, 0,0,0,0, 1,1, 1.0f);
    mm_kernel<false,false,false><<<dim3((NKV*HD)/128, MTOK/128, 1), 256>>>(
        x3, vw3, Vb, nullptr, 3*DMODEL, 3*DMODEL, 3*DMODEL, NKV*HD, 0,0,0,0, 1,1, 1.0f);

    // norm/rope/gain; V transpose
    postproc_qk<true ><<<dim3(MTOK, NH),  128>>>(Qb, Qp3, q_g,     NH);
    postproc_qk<false><<<dim3(MTOK, NKV), 128>>>(Kb, Kp3, nullptr, NKV);
    transpose_v<<<dim3(MTOK, NKV), 128>>>(Vb, Vt3);

    // scores = Qp @ Kp^T * scale, causal. K3 = 3*HD = 384
    mm_kernel<true,false,false><<<dim3(SEQ/128, SEQ/128, BATCH*NH), 256>>>(
        Qp3, Kp3, Sb, nullptr, 3*HD, 3*HD, 3*HD, SEQ,
        (long long)SEQ*3*HD, (long long)SEQ*3*HD, SS, 0, 4, 1, scale);

    // softmax -> triple bf16 P3
    softmax_kernel<<<BATCH*NH*SEQ, 256>>>(Sb, P3);

    // Y = P @ Vt^T (causal K bound), triple bf16 out at [b, s, 3*(h*128+d)]
    mm_kernel<false,true,true><<<dim3(HD/128, SEQ/128, BATCH*NH), 256>>>(
        P3, Vt3, nullptr, Y3, 3*SEQ, 3*SEQ, 3*SEQ, 3*DMODEL,
        (long long)SEQ*3*SEQ, (long long)HD*3*SEQ, (long long)SEQ*3*DMODEL, 3*HD, 4, NH, 1.0f);

    // out = Y @ out_w^T (fp32 into d_out), K3 = 3*DMODEL
    mm_kernel<false,false,false><<<dim3(DMODEL/128, MTOK/128, 1), 256>>>(
        Y3, ow3, out, nullptr, 3*DMODEL, 3*DMODEL, 3*DMODEL, DMODEL, 0,0,0,0, 1,1, 1.0f);
}

// round 6
// speedup vs baseline: 1.9717x; 1.0762x over previous
#include <cuda_runtime.h>
#include <cuda_bf16.h>
#include <cstdint>
#include <math.h>

#define BATCH 2
#define SEQ   2048
#define DMODEL 2048
#define NH    16
#define NKV   4
#define HD    128
#define ROPE  64
#define MTOK  (BATCH*SEQ)
#define EPSV  1.1920929e-07f

typedef __nv_bfloat16 bf16;

// ---------------- scratch (triple-interleaved hi/lo bf16 along K) ----------------
// A-side pattern per element: (hi, lo, hi). B-side pattern: (hi, hi, lo).
__device__ bf16 g_x3 [(size_t)MTOK*3*DMODEL];
__device__ bf16 g_qw3[(size_t)DMODEL*3*DMODEL];
__device__ bf16 g_kw3[(size_t)NKV*HD*3*DMODEL];
__device__ bf16 g_vw3[(size_t)NKV*HD*3*DMODEL];
__device__ bf16 g_ow3[(size_t)DMODEL*3*DMODEL];
__device__ float g_Qb[(size_t)MTOK*DMODEL];
__device__ float g_Kb[(size_t)MTOK*NKV*HD];
__device__ float g_Vb[(size_t)MTOK*NKV*HD];
__device__ bf16 g_Qp3[(size_t)BATCH*NH*SEQ*3*HD];
__device__ bf16 g_Kp3[(size_t)BATCH*NKV*SEQ*3*HD];
__device__ bf16 g_Vt3[(size_t)BATCH*NKV*HD*3*SEQ];
__device__ float g_S [(size_t)BATCH*NH*SEQ*SEQ];
__device__ bf16 g_P3 [(size_t)BATCH*NH*SEQ*3*SEQ];
__device__ bf16 g_Y3 [(size_t)MTOK*3*DMODEL];

__device__ __forceinline__ void split2(float v, bf16& h, bf16& l) {
    h = __float2bfloat16_rn(v);
    l = __float2bfloat16_rn(v - __bfloat162float(h));
}
__device__ __forceinline__ uint32_t pk(bf16 a, bf16 b) {
    return (uint32_t)__bfloat16_as_ushort(a) | ((uint32_t)__bfloat16_as_ushort(b) << 16);
}

// ---------------- PTX helpers (baseline PTX only) ----------------
__device__ __forceinline__ uint32_t smem_u32(const void* p) {
    uint32_t a;
    asm("{ .reg .u64 t; cvta.to.shared.u64 t, %1; cvt.u32.u64 %0, t; }" : "=r"(a) : "l"(p));
    return a;
}
__device__ __forceinline__ void ldsm4(uint32_t* r, uint32_t addr) {
    asm volatile("ldmatrix.sync.aligned.m8n8.x4.shared.b16 {%0,%1,%2,%3}, [%4];"
                 : "=r"(r[0]), "=r"(r[1]), "=r"(r[2]), "=r"(r[3]) : "r"(addr));
}
__device__ __forceinline__ void mma16816(float* c, const uint32_t* a, const uint32_t* b) {
    asm volatile(
        "mma.sync.aligned.m16n8k16.row.col.f32.bf16.bf16.f32 "
        "{%0,%1,%2,%3}, {%4,%5,%6,%7}, {%8,%9}, {%0,%1,%2,%3};"
        : "+f"(c[0]), "+f"(c[1]), "+f"(c[2]), "+f"(c[3])
        : "r"(a[0]), "r"(a[1]), "r"(a[2]), "r"(a[3]), "r"(b[0]), "r"(b[1]));
}
#define CP_ASYNC16(dst, src) \
    asm volatile("cp.async.cg.shared.global [%0], [%1], 16;" :: "r"(dst), "l"(src) : "memory")
#define CP_COMMIT() asm volatile("cp.async.commit_group;" ::: "memory")
#define CP_WAIT(n)  asm volatile("cp.async.wait_group %0;" :: "n"(n) : "memory")

// ---------------- bf16 mma GEMM over interleaved K3 ----------------
// 128x128x32 tiles, 8 warps (64x32 warp tiles), 3-stage cp.async pipeline.
#define PADK 40
#define TILEB (128*PADK*2)            // 10240 B per buffer per matrix
#define MM_SMEM (3*TILEB*2)           // 61440 B dynamic

template<bool CAUSAL, bool CAUSAL_K, bool BF16_OUT>
__global__ void __launch_bounds__(256, 2) mm_kernel(
    const bf16* __restrict__ A, const bf16* __restrict__ B,
    float* __restrict__ C, bf16* __restrict__ C3,
    int K3, int lda, int ldb, int ldc,
    long long sA, long long sB, long long sC, long long sC2,
    int bDiv, int cDiv, float alpha)
{
    extern __shared__ __align__(16) char smem[];
    bf16* shA = reinterpret_cast<bf16*>(smem);                 // 3 bufs
    bf16* shB = reinterpret_cast<bf16*>(smem + 3 * TILEB);     // 3 bufs
    const uint32_t sAaddr = smem_u32(shA);
    const uint32_t sBaddr = smem_u32(shB);

    const int z = blockIdx.z;
    A += (long long)z * sA;
    B += (long long)(z / bDiv) * sB;
    const long long cOff = (long long)(z / cDiv) * sC + (long long)(z % cDiv) * sC2;

    const int m0 = blockIdx.y * 128;
    const int n0 = blockIdx.x * 128;
    if (CAUSAL && n0 > m0 + 127) return;

    const int t = threadIdx.x;
    const int w = t >> 5, lane = t & 31;
    const int wr = w >> 2, wc = w & 3;          // 2x4 warp grid
    const int mBase = wr * 64, nBase = wc * 32;

    const int aRow = mBase + (lane & 7) + ((lane >> 3) & 1) * 8;
    const int aK   = (lane >> 4) * 8;
    const int bRow = nBase + (lane & 7) + ((lane >> 4) & 1) * 8;
    const int bK   = ((lane >> 3) & 1) * 8;

    const int lr = t >> 1;
    const int lc = (t & 1) * 2;

    int kEnd = K3;
    if (CAUSAL_K) { int ke = 3 * (m0 + 128); kEnd = (ke < K3) ? ke : K3; }
    const int nc = kEnd >> 5;

    const bf16* gA = A + (long long)(m0 + lr) * lda + lc * 8;
    const bf16* gB = B + (long long)(n0 + lr) * ldb + lc * 8;
    const uint32_t dA = sAaddr + (lr * PADK + lc * 8) * 2;
    const uint32_t dB = sBaddr + (lr * PADK + lc * 8) * 2;

    float acc[4][4][4];
    #pragma unroll
    for (int i = 0; i < 4; i++)
        #pragma unroll
        for (int j = 0; j < 4; j++)
            #pragma unroll
            for (int q = 0; q < 4; q++) acc[i][j][q] = 0.0f;

    // prologue: prefetch chunks 0,1 into bufs 0,1
    #pragma unroll
    for (int j = 0; j < 2; j++) {
        if (j < nc) {
            const bf16* pA = gA + j * 32;
            const bf16* pB = gB + j * 32;
            CP_ASYNC16(dA + j * TILEB, pA);      CP_ASYNC16(dA + j * TILEB + 16, pA + 8);
            CP_ASYNC16(dB + j * TILEB, pB);      CP_ASYNC16(dB + j * TILEB + 16, pB + 8);
        }
        CP_COMMIT();
    }

    int buf = 0, nbuf = 2;
    for (int i = 0; i < nc; i++) {
        if (i < nc - 1) { CP_WAIT(1); } else { CP_WAIT(0); }
        __syncthreads();

        // issue chunk i+2 into buf (i+2)%3 (safe: all threads are past compute of i-1)
        if (i + 2 < nc) {
            const bf16* pA = gA + (i + 2) * 32;
            const bf16* pB = gB + (i + 2) * 32;
            CP_ASYNC16(dA + nbuf * TILEB, pA);      CP_ASYNC16(dA + nbuf * TILEB + 16, pA + 8);
            CP_ASYNC16(dB + nbuf * TILEB, pB);      CP_ASYNC16(dB + nbuf * TILEB + 16, pB + 8);
        }
        CP_COMMIT();

        const uint32_t ab = sAaddr + buf * TILEB;
        const uint32_t bb = sBaddr + buf * TILEB;
        #pragma unroll
        for (int ks = 0; ks < 2; ks++) {
            uint32_t af[4][4], bfr[2][4];
            #pragma unroll
            for (int fm = 0; fm < 4; fm++)
                ldsm4(af[fm], ab + ((aRow + fm * 16) * PADK + ks * 16 + aK) * 2);
            #pragma unroll
            for (int bg = 0; bg < 2; bg++)
                ldsm4(bfr[bg], bb + ((bRow + bg * 16) * PADK + ks * 16 + bK) * 2);
            #pragma unroll
            for (int fm = 0; fm < 4; fm++)
                #pragma unroll
                for (int fn = 0; fn < 4; fn++)
                    mma16816(acc[fm][fn], af[fm], &bfr[fn >> 1][(fn & 1) * 2]);
        }

        buf = (buf == 2) ? 0 : buf + 1;
        nbuf = (nbuf == 2) ? 0 : nbuf + 1;
    }

    const int g = lane >> 2, tg = lane & 3;
    #pragma unroll
    for (int fm = 0; fm < 4; fm++) {
        #pragma unroll
        for (int fn = 0; fn < 4; fn++) {
            const int col = n0 + nBase + fn * 8 + tg * 2;
            #pragma unroll
            for (int half = 0; half < 2; half++) {
                const int row = m0 + mBase + fm * 16 + g + half * 8;
                float v0 = acc[fm][fn][half * 2]     * alpha;
                float v1 = acc[fm][fn][half * 2 + 1] * alpha;
                if (BF16_OUT) {
                    bf16 h0, l0, h1, l1;
                    split2(v0, h0, l0); split2(v1, h1, l1);
                    uint32_t* dst = reinterpret_cast<uint32_t*>(
                        C3 + cOff + (long long)row * ldc + 3 * col);
                    dst[0] = pk(h0, l0);
                    dst[1] = pk(h0, h1);
                    dst[2] = pk(l1, h1);
                } else {
                    if (CAUSAL) {
                        if (col     > row) v0 = -1e30f;
                        if (col + 1 > row) v1 = -1e30f;
                    }
                    float2 f; f.x = v0; f.y = v1;
                    *reinterpret_cast<float2*>(C + cOff + (long long)row * ldc + col) = f;
                }
            }
        }
    }
}

// ---------------- fp32 -> triple-interleaved bf16 ----------------
template<bool ASIDE>
__global__ void split3_kernel(const float* __restrict__ in, bf16* __restrict__ o3, long long n4)
{
    long long i = (long long)blockIdx.x * blockDim.x + threadIdx.x;
    if (i >= n4) return;
    float4 v = reinterpret_cast<const float4*>(in)[i];
    bf16 h[4], l[4];
    split2(v.x, h[0], l[0]); split2(v.y, h[1], l[1]);
    split2(v.z, h[2], l[2]); split2(v.w, h[3], l[3]);
    uint32_t u[6];
    if (ASIDE) {
        u[0] = pk(h[0], l[0]); u[1] = pk(h[0], h[1]); u[2] = pk(l[1], h[1]);
        u[3] = pk(h[2], l[2]); u[4] = pk(h[2], h[3]); u[5] = pk(l[3], h[3]);
    } else {
        u[0] = pk(h[0], h[0]); u[1] = pk(l[0], h[1]); u[2] = pk(h[1], l[1]);
        u[3] = pk(h[2], h[2]); u[4] = pk(l[2], h[3]); u[5] = pk(h[3], l[3]);
    }
    uint2* dst = reinterpret_cast<uint2*>(o3 + i * 12);
    dst[0] = make_uint2(u[0], u[1]);
    dst[1] = make_uint2(u[2], u[3]);
    dst[2] = make_uint2(u[4], u[5]);
}

// ---------------- RMSNorm + RoPE + gain -> triple bf16 [b,h,s,3d] ----------------
template<bool ASIDE>
__global__ void postproc_qk(const float* __restrict__ in, bf16* __restrict__ o3,
                            const float* __restrict__ gain, int nHeads)
{
    const int m = blockIdx.x, h = blockIdx.y, d = threadIdx.x;
    const int b = m / SEQ, s = m % SEQ;
    float v = in[(long long)m * (nHeads * HD) + h * HD + d];

    __shared__ float red[128];
    __shared__ float vec[128];
    red[d] = v * v;
    __syncthreads();
    #pragma unroll
    for (int off = 64; off > 0; off >>= 1) {
        if (d < off) red[d] += red[d + off];
        __syncthreads();
    }
    float ms = red[0] * (1.0f / 128.0f);
    v = v * rsqrtf(ms + EPSV);
    vec[d] = v;
    __syncthreads();
    if (d < ROPE) {
        int j = d & 31;
        float inv_freq = powf(10000.0f, -(float)j / 32.0f);
        float ang = (float)s * inv_freq;
        float c = cosf(ang), sn = sinf(ang);
        float x1 = vec[j], x2 = vec[j + 32];
        v = (d < 32) ? (x1 * c + x2 * sn) : (-x1 * sn + x2 * c);
    }
    if (gain) v *= gain[h];

    bf16 hh, ll; split2(v, hh, ll);
    bf16* o = o3 + ((long long)(b * nHeads + h) * SEQ + s) * (3 * HD) + 3 * d;
    if (ASIDE) { o[0] = hh; o[1] = ll; o[2] = hh; }
    else       { o[0] = hh; o[1] = hh; o[2] = ll; }
}

// ---------------- V: split + transpose to [b,kv,d,3s] (B-side) ----------------
__global__ void transpose_v(const float* __restrict__ in, bf16* __restrict__ o3)
{
    const int m = blockIdx.x, h = blockIdx.y, d = threadIdx.x;
    const int b = m / SEQ, s = m % SEQ;
    float v = in[(long long)m * (NKV * HD) + h * HD + d];
    bf16 hh, ll; split2(v, hh, ll);
    bf16* o = o3 + ((long long)(b * NKV + h) * HD + d) * (3 * SEQ) + 3 * s;
    o[0] = hh; o[1] = hh; o[2] = ll;
}

// ---------------- causal softmax (work-bounded): fp32 S (pre-scaled by log2e) -> P3 ----------------
__global__ void softmax_kernel(const float* __restrict__ S, bf16* __restrict__ P3)
{
    const int r = blockIdx.x % SEQ;
    const float* p = S + (long long)blockIdx.x * SEQ;
    bf16* q3 = P3 + (long long)blockIdx.x * (3 * SEQ);
    const int t = threadIdx.x;                      // 256
    const int nIter = (r >> 8) + 1;                 // valid 256-octets
    const int tileEnd = ((r >> 7) + 1) << 7;        // store bound (128-aligned)

    float v[8];
    float m = -3.4e38f;
    for (int i = 0; i < nIter; i++) {
        int j = t + i * 256;
        v[i] = (j <= r) ? p[j] : -3.4e38f;
        m = fmaxf(m, v[i]);
    }

    __shared__ float red[256];
    red[t] = m; __syncthreads();
    #pragma unroll
    for (int off = 128; off > 0; off >>= 1) {
        if (t < off) red[t] = fmaxf(red[t], red[t + off]);
        __syncthreads();
    }
    m = red[0];
    __syncthreads();

    float s = 0.0f;
    for (int i = 0; i < nIter; i++) { v[i] = exp2f(v[i] - m); s += v[i]; }
    red[t] = s; __syncthreads();
    #pragma unroll
    for (int off = 128; off > 0; off >>= 1) {
        if (t < off) red[t] += red[t + off];
        __syncthreads();
    }
    const float inv = 1.0f / red[0];
    for (int i = 0; i < nIter; i++) {
        int j = t + i * 256;
        if (j < tileEnd) {
            bf16 hh, ll; split2(v[i] * inv, hh, ll);
            bf16* o = q3 + 3 * j;
            o[0] = hh; o[1] = ll; o[2] = hh;
        }
    }
}

// ---------------- launch ----------------
extern "C" void kernel_launch(void* const* d_in, const int* in_sizes, int n_in,
                              void* d_out, int out_size)
{
    const float* x     = (const float*)d_in[0];
    const float* q_w   = (const float*)d_in[1];
    const float* k_w   = (const float*)d_in[2];
    const float* v_w   = (const float*)d_in[3];
    const float* out_w = (const float*)d_in[4];
    const float* q_g   = (const float*)d_in[5];
    float* out = (float*)d_out;

    static bool init = false;
    static bf16 *x3,*qw3,*kw3,*vw3,*ow3,*Qp3,*Kp3,*Vt3,*P3,*Y3;
    static float *Qb,*Kb,*Vb,*Sb;
    if (!init) {
        cudaGetSymbolAddress((void**)&x3,  g_x3);
        cudaGetSymbolAddress((void**)&qw3, g_qw3);
        cudaGetSymbolAddress((void**)&kw3, g_kw3);
        cudaGetSymbolAddress((void**)&vw3, g_vw3);
        cudaGetSymbolAddress((void**)&ow3, g_ow3);
        cudaGetSymbolAddress((void**)&Qb,  g_Qb);
        cudaGetSymbolAddress((void**)&Kb,  g_Kb);
        cudaGetSymbolAddress((void**)&Vb,  g_Vb);
        cudaGetSymbolAddress((void**)&Qp3, g_Qp3);
        cudaGetSymbolAddress((void**)&Kp3, g_Kp3);
        cudaGetSymbolAddress((void**)&Vt3, g_Vt3);
        cudaGetSymbolAddress((void**)&Sb,  g_S);
        cudaGetSymbolAddress((void**)&P3,  g_P3);
        cudaGetSymbolAddress((void**)&Y3,  g_Y3);
        cudaFuncSetAttribute(mm_kernel<false,false,false>, cudaFuncAttributeMaxDynamicSharedMemorySize, MM_SMEM);
        cudaFuncSetAttribute(mm_kernel<true, false,false>, cudaFuncAttributeMaxDynamicSharedMemorySize, MM_SMEM);
        cudaFuncSetAttribute(mm_kernel<false,true, true >, cudaFuncAttributeMaxDynamicSharedMemorySize, MM_SMEM);
        init = true;
    }

    const long long SS = (long long)SEQ * SEQ;
    // scores pre-scaled by log2(e) so softmax can use exp2f
    const float scale2 = 0.08838834764831845f * 1.4426950408889634f;

    {
        long long n4;
        n4 = (long long)MTOK * DMODEL / 4;   split3_kernel<true ><<<(unsigned)((n4+255)/256),256>>>(x, x3, n4);
        n4 = (long long)DMODEL * DMODEL / 4; split3_kernel<false><<<(unsigned)((n4+255)/256),256>>>(q_w, qw3, n4);
        n4 = (long long)NKV*HD * DMODEL / 4; split3_kernel<false><<<(unsigned)((n4+255)/256),256>>>(k_w, kw3, n4);
        n4 = (long long)NKV*HD * DMODEL / 4; split3_kernel<false><<<(unsigned)((n4+255)/256),256>>>(v_w, vw3, n4);
        n4 = (long long)DMODEL * DMODEL / 4; split3_kernel<false><<<(unsigned)((n4+255)/256),256>>>(out_w, ow3, n4);
    }

    // QKV projections (fp32 out), K3 = 3*DMODEL
    mm_kernel<false,false,false><<<dim3(DMODEL/128, MTOK/128, 1), 256, MM_SMEM>>>(
        x3, qw3, Qb, nullptr, 3*DMODEL, 3*DMODEL, 3*DMODEL, DMODEL, 0,0,0,0, 1,1, 1.0f);
    mm_kernel<false,false,false><<<dim3((NKV*HD)/128, MTOK/128, 1), 256, MM_SMEM>>>(
        x3, kw3, Kb, nullptr, 3*DMODEL, 3*DMODEL, 3*DMODEL, NKV*HD, 0,0,0,0, 1,1, 1.0f);
    mm_kernel<false,false,false><<<dim3((NKV*HD)/128, MTOK/128, 1), 256, MM_SMEM>>>(
        x3, vw3, Vb, nullptr, 3*DMODEL, 3*DMODEL, 3*DMODEL, NKV*HD, 0,0,0,0, 1,1, 1.0f);

    postproc_qk<true ><<<dim3(MTOK, NH),  128>>>(Qb, Qp3, q_g,     NH);
    postproc_qk<false><<<dim3(MTOK, NKV), 128>>>(Kb, Kp3, nullptr, NKV);
    transpose_v<<<dim3(MTOK, NKV), 128>>>(Vb, Vt3);

    // scores = Qp @ Kp^T * scale * log2e, causal. K3 = 384
    mm_kernel<true,false,false><<<dim3(SEQ/128, SEQ/128, BATCH*NH), 256, MM_SMEM>>>(
        Qp3, Kp3, Sb, nullptr, 3*HD, 3*HD, 3*HD, SEQ,
        (long long)SEQ*3*HD, (long long)SEQ*3*HD, SS, 0, 4, 1, scale2);

    softmax_kernel<<<BATCH*NH*SEQ, 256>>>(Sb, P3);

    // Y = P @ Vt^T (causal K bound), triple bf16 out
    mm_kernel<false,true,true><<<dim3(HD/128, SEQ/128, BATCH*NH), 256, MM_SMEM>>>(
        P3, Vt3, nullptr, Y3, 3*SEQ, 3*SEQ, 3*SEQ, 3*DMODEL,
        (long long)SEQ*3*SEQ, (long long)HD*3*SEQ, (long long)SEQ*3*DMODEL, 3*HD, 4, NH, 1.0f);

    // out = Y @ out_w^T (fp32 into d_out)
    mm_kernel<false,false,false><<<dim3(DMODEL/128, MTOK/128, 1), 256, MM_SMEM>>>(
        Y3, ow3, out, nullptr, 3*DMODEL, 3*DMODEL, 3*DMODEL, DMODEL, 0,0,0,0, 1,1, 1.0f);
}

// round 7
// speedup vs baseline: 2.1469x; 1.0888x over previous
#include <cuda_runtime.h>
#include <cuda_bf16.h>
#include <cstdint>
#include <math.h>

#define BATCH 2
#define SEQ   2048
#define DMODEL 2048
#define NH    16
#define NKV   4
#define HD    128
#define ROPE  64
#define MTOK  (BATCH*SEQ)
#define EPSV  1.1920929e-07f

typedef __nv_bfloat16 bf16;

// ---------------- scratch (triple-interleaved hi/lo bf16 along K) ----------------
// A-side pattern per element: (hi, lo, hi). B-side pattern: (hi, hi, lo).
__device__ bf16 g_x3 [(size_t)MTOK*3*DMODEL];
__device__ bf16 g_qw3[(size_t)DMODEL*3*DMODEL];
__device__ bf16 g_kw3[(size_t)NKV*HD*3*DMODEL];
__device__ bf16 g_vw3[(size_t)NKV*HD*3*DMODEL];
__device__ bf16 g_ow3[(size_t)DMODEL*3*DMODEL];
__device__ float g_Qb[(size_t)MTOK*DMODEL];
__device__ float g_Kb[(size_t)MTOK*NKV*HD];
__device__ float g_Vb[(size_t)MTOK*NKV*HD];
__device__ bf16 g_Qp3[(size_t)BATCH*NH*SEQ*3*HD];
__device__ bf16 g_Kp3[(size_t)BATCH*NKV*SEQ*3*HD];
__device__ bf16 g_Vt3[(size_t)BATCH*NKV*HD*3*SEQ];
__device__ float g_S [(size_t)BATCH*NH*SEQ*SEQ];
__device__ bf16 g_Y3 [(size_t)MTOK*3*DMODEL];

__device__ __forceinline__ void split2(float v, bf16& h, bf16& l) {
    h = __float2bfloat16_rn(v);
    l = __float2bfloat16_rn(v - __bfloat162float(h));
}
__device__ __forceinline__ uint32_t pk(bf16 a, bf16 b) {
    return (uint32_t)__bfloat16_as_ushort(a) | ((uint32_t)__bfloat16_as_ushort(b) << 16);
}

// ---------------- PTX helpers (baseline PTX only) ----------------
__device__ __forceinline__ uint32_t smem_u32(const void* p) {
    uint32_t a;
    asm("{ .reg .u64 t; cvta.to.shared.u64 t, %1; cvt.u32.u64 %0, t; }" : "=r"(a) : "l"(p));
    return a;
}
__device__ __forceinline__ void ldsm4(uint32_t* r, uint32_t addr) {
    asm volatile("ldmatrix.sync.aligned.m8n8.x4.shared.b16 {%0,%1,%2,%3}, [%4];"
                 : "=r"(r[0]), "=r"(r[1]), "=r"(r[2]), "=r"(r[3]) : "r"(addr));
}
__device__ __forceinline__ void mma16816(float* c, const uint32_t* a, const uint32_t* b) {
    asm volatile(
        "mma.sync.aligned.m16n8k16.row.col.f32.bf16.bf16.f32 "
        "{%0,%1,%2,%3}, {%4,%5,%6,%7}, {%8,%9}, {%0,%1,%2,%3};"
        : "+f"(c[0]), "+f"(c[1]), "+f"(c[2]), "+f"(c[3])
        : "r"(a[0]), "r"(a[1]), "r"(a[2]), "r"(a[3]), "r"(b[0]), "r"(b[1]));
}
#define CP_ASYNC16(dst, src) \
    asm volatile("cp.async.cg.shared.global [%0], [%1], 16;" :: "r"(dst), "l"(src) : "memory")
#define CP_COMMIT() asm volatile("cp.async.commit_group;" ::: "memory")
#define CP_WAIT(n)  asm volatile("cp.async.wait_group %0;" :: "n"(n) : "memory")

// ---------------- bf16 mma GEMM over interleaved K3 (projections/score/out) ----------------
#define PADK 40
#define TILEB (128*PADK*2)            // 10240 B
#define MM_SMEM (3*TILEB*2)           // 61440 B

template<bool CAUSAL, bool BF16_OUT>
__global__ void __launch_bounds__(256, 2) mm_kernel(
    const bf16* __restrict__ A, const bf16* __restrict__ B,
    float* __restrict__ C, bf16* __restrict__ C3,
    int K3, int lda, int ldb, int ldc,
    long long sA, long long sB, long long sC, long long sC2,
    int bDiv, int cDiv, float alpha)
{
    extern __shared__ __align__(16) char smem[];
    bf16* shA = reinterpret_cast<bf16*>(smem);
    bf16* shB = reinterpret_cast<bf16*>(smem + 3 * TILEB);
    const uint32_t sAaddr = smem_u32(shA);
    const uint32_t sBaddr = smem_u32(shB);

    const int z = blockIdx.z;
    A += (long long)z * sA;
    B += (long long)(z / bDiv) * sB;
    const long long cOff = (long long)(z / cDiv) * sC + (long long)(z % cDiv) * sC2;

    const int m0 = blockIdx.y * 128;
    const int n0 = blockIdx.x * 128;
    if (CAUSAL && n0 > m0 + 127) return;

    const int t = threadIdx.x;
    const int w = t >> 5, lane = t & 31;
    const int wr = w >> 2, wc = w & 3;
    const int mBase = wr * 64, nBase = wc * 32;

    const int aRow = mBase + (lane & 7) + ((lane >> 3) & 1) * 8;
    const int aK   = (lane >> 4) * 8;
    const int bRow = nBase + (lane & 7) + ((lane >> 4) & 1) * 8;
    const int bK   = ((lane >> 3) & 1) * 8;

    const int lr = t >> 1;
    const int lc = (t & 1) * 2;

    const int nc = K3 >> 5;

    const bf16* gA = A + (long long)(m0 + lr) * lda + lc * 8;
    const bf16* gB = B + (long long)(n0 + lr) * ldb + lc * 8;
    const uint32_t dA = sAaddr + (lr * PADK + lc * 8) * 2;
    const uint32_t dB = sBaddr + (lr * PADK + lc * 8) * 2;

    float acc[4][4][4];
    #pragma unroll
    for (int i = 0; i < 4; i++)
        #pragma unroll
        for (int j = 0; j < 4; j++)
            #pragma unroll
            for (int q = 0; q < 4; q++) acc[i][j][q] = 0.0f;

    #pragma unroll
    for (int j = 0; j < 2; j++) {
        if (j < nc) {
            const bf16* pA = gA + j * 32;
            const bf16* pB = gB + j * 32;
            CP_ASYNC16(dA + j * TILEB, pA);      CP_ASYNC16(dA + j * TILEB + 16, pA + 8);
            CP_ASYNC16(dB + j * TILEB, pB);      CP_ASYNC16(dB + j * TILEB + 16, pB + 8);
        }
        CP_COMMIT();
    }

    int buf = 0, nbuf = 2;
    for (int i = 0; i < nc; i++) {
        if (i < nc - 1) { CP_WAIT(1); } else { CP_WAIT(0); }
        __syncthreads();

        if (i + 2 < nc) {
            const bf16* pA = gA + (i + 2) * 32;
            const bf16* pB = gB + (i + 2) * 32;
            CP_ASYNC16(dA + nbuf * TILEB, pA);      CP_ASYNC16(dA + nbuf * TILEB + 16, pA + 8);
            CP_ASYNC16(dB + nbuf * TILEB, pB);      CP_ASYNC16(dB + nbuf * TILEB + 16, pB + 8);
        }
        CP_COMMIT();

        const uint32_t ab = sAaddr + buf * TILEB;
        const uint32_t bb = sBaddr + buf * TILEB;
        #pragma unroll
        for (int ks = 0; ks < 2; ks++) {
            uint32_t af[4][4], bfr[2][4];
            #pragma unroll
            for (int fm = 0; fm < 4; fm++)
                ldsm4(af[fm], ab + ((aRow + fm * 16) * PADK + ks * 16 + aK) * 2);
            #pragma unroll
            for (int bg = 0; bg < 2; bg++)
                ldsm4(bfr[bg], bb + ((bRow + bg * 16) * PADK + ks * 16 + bK) * 2);
            #pragma unroll
            for (int fm = 0; fm < 4; fm++)
                #pragma unroll
                for (int fn = 0; fn < 4; fn++)
                    mma16816(acc[fm][fn], af[fm], &bfr[fn >> 1][(fn & 1) * 2]);
        }

        buf = (buf == 2) ? 0 : buf + 1;
        nbuf = (nbuf == 2) ? 0 : nbuf + 1;
    }

    const int g = lane >> 2, tg = lane & 3;
    #pragma unroll
    for (int fm = 0; fm < 4; fm++) {
        #pragma unroll
        for (int fn = 0; fn < 4; fn++) {
            const int col = n0 + nBase + fn * 8 + tg * 2;
            #pragma unroll
            for (int half = 0; half < 2; half++) {
                const int row = m0 + mBase + fm * 16 + g + half * 8;
                float v0 = acc[fm][fn][half * 2]     * alpha;
                float v1 = acc[fm][fn][half * 2 + 1] * alpha;
                if (BF16_OUT) {
                    bf16 h0, l0, h1, l1;
                    split2(v0, h0, l0); split2(v1, h1, l1);
                    uint32_t* dst = reinterpret_cast<uint32_t*>(
                        C3 + cOff + (long long)row * ldc + 3 * col);
                    dst[0] = pk(h0, l0);
                    dst[1] = pk(h0, h1);
                    dst[2] = pk(l1, h1);
                } else {
                    if (CAUSAL) {
                        if (col     > row) v0 = -1e30f;
                        if (col + 1 > row) v1 = -1e30f;
                    }
                    float2 f; f.x = v0; f.y = v1;
                    *reinterpret_cast<float2*>(C + cOff + (long long)row * ldc + col) = f;
                }
            }
        }
    }
}

// ---------------- fused softmax + PV kernel ----------------
// One CTA per (head z, 128-row m-block). Computes O = softmax(S_row) @ V and
// writes Y3 triple bf16. A-operand (P) is produced in-kernel from S (fp32,
// pre-scaled by log2e): exp2 once per element, triple-split into smem.
// Chunk = 48 k3 slots = 16 real columns. V streamed via cp.async (3 bufs).
#define FK3 48
#define FPAD 56
#define FTILE (128*FPAD*2)            // 14336 B per buf
#define FV_SMEM (6*FTILE + 512 + 1024)

__global__ void __launch_bounds__(256, 1) pv_fused(
    const float* __restrict__ S, const bf16* __restrict__ Vt, bf16* __restrict__ Y3)
{
    extern __shared__ __align__(16) char smem[];
    bf16* shA = reinterpret_cast<bf16*>(smem);                  // 3 bufs (P triple)
    bf16* shB = reinterpret_cast<bf16*>(smem + 3 * FTILE);      // 3 bufs (V)
    float* mrow = reinterpret_cast<float*>(smem + 6 * FTILE);   // 128 (rowmax, later 1/l)
    float* sums = mrow + 128;                                   // 256
    const uint32_t sAaddr = smem_u32(shA);
    const uint32_t sBaddr = smem_u32(shB);

    const int z  = blockIdx.x;                       // b*NH + h
    const int my = (gridDim.y - 1) - blockIdx.y;     // longest first
    const int m0 = my * 128;
    const int kEnd = m0 + 128;                       // valid columns
    const int nch = kEnd >> 4;                       // 16 real cols per chunk

    const float* Sb = S + (long long)z * SEQ * SEQ + (long long)m0 * SEQ;
    const bf16*  Vb = Vt + (long long)(z >> 2) * HD * 3 * SEQ;
    bf16* Yb = Y3 + (long long)(z >> 4) * SEQ * 3 * DMODEL + (long long)(z & 15) * 3 * HD;

    const int t = threadIdx.x;
    const int w = t >> 5, lane = t & 31;

    // ---- pass 1: per-row max (no exp) ----
    for (int rr = 0; rr < 16; rr++) {
        const int row = w * 16 + rr;
        const float* p = Sb + (long long)row * SEQ;
        float m = -3.4e38f;
        for (int c = lane * 4; c < kEnd; c += 128) {
            float4 v = *reinterpret_cast<const float4*>(p + c);
            m = fmaxf(m, fmaxf(fmaxf(v.x, v.y), fmaxf(v.z, v.w)));
        }
        #pragma unroll
        for (int off = 16; off > 0; off >>= 1)
            m = fmaxf(m, __shfl_xor_sync(0xFFFFFFFFu, m, off));
        if (lane == 0) mrow[row] = m;
    }
    __syncthreads();

    // ---- fill state (each thread owns one row-half across all chunks) ----
    const int frow = t >> 1, fhalf = t & 1;
    const float mreg = mrow[frow];
    float sumReg = 0.0f;
    const float* fS = Sb + (long long)frow * SEQ + fhalf * 8;     // + chunk*16
    uint32_t* aU = reinterpret_cast<uint32_t*>(shA) + frow * (FPAD / 2) + fhalf * 12;
    const int aBufU = FTILE / 4;

    // V cp.async mapping: thread -> (d-row t>>1, 3 x 16B)
    const bf16* gV = Vb + (long long)frow * (3 * SEQ) + fhalf * 24;   // + chunk*48
    const uint32_t dV = sBaddr + (frow * FPAD + fhalf * 24) * 2;

    // mma lane mapping (2x4 warp grid, warp tile 64x32)
    const int wr = w >> 2, wc = w & 3;
    const int mBase = wr * 64, nBase = wc * 32;
    const int aRow = mBase + (lane & 7) + ((lane >> 3) & 1) * 8;
    const int aK   = (lane >> 4) * 8;
    const int bRow = nBase + (lane & 7) + ((lane >> 4) & 1) * 8;
    const int bK   = ((lane >> 3) & 1) * 8;

    float acc[4][4][4];
    #pragma unroll
    for (int i = 0; i < 4; i++)
        #pragma unroll
        for (int j = 0; j < 4; j++)
            #pragma unroll
            for (int q = 0; q < 4; q++) acc[i][j][q] = 0.0f;

    // fill chunk c into A buf
    auto fillA = [&](int c, int buf) {
        const float* sp = fS + c * 16;
        float4 v0 = *reinterpret_cast<const float4*>(sp);
        float4 v1 = *reinterpret_cast<const float4*>(sp + 4);
        float pv[8];
        pv[0] = exp2f(v0.x - mreg); pv[1] = exp2f(v0.y - mreg);
        pv[2] = exp2f(v0.z - mreg); pv[3] = exp2f(v0.w - mreg);
        pv[4] = exp2f(v1.x - mreg); pv[5] = exp2f(v1.y - mreg);
        pv[6] = exp2f(v1.z - mreg); pv[7] = exp2f(v1.w - mreg);
        #pragma unroll
        for (int j = 0; j < 8; j++) sumReg += pv[j];
        uint32_t* dst = aU + buf * aBufU;
        #pragma unroll
        for (int j = 0; j < 4; j++) {
            bf16 h0, l0, h1, l1;
            split2(pv[2 * j],     h0, l0);
            split2(pv[2 * j + 1], h1, l1);
            dst[3 * j]     = pk(h0, l0);
            dst[3 * j + 1] = pk(h0, h1);
            dst[3 * j + 2] = pk(l1, h1);
        }
    };
    auto loadV = [&](int c, int buf) {
        const bf16* pv = gV + c * 48;
        const uint32_t d = dV + buf * FTILE;
        CP_ASYNC16(d,      pv);
        CP_ASYNC16(d + 16, pv + 8);
        CP_ASYNC16(d + 32, pv + 16);
    };

    // prologue: chunks 0,1 -> bufs 0,1
    fillA(0, 0); fillA(1, 1);
    loadV(0, 0); CP_COMMIT();
    loadV(1, 1); CP_COMMIT();

    int buf = 0, nbuf = 2;
    for (int i = 0; i < nch; i++) {
        if (i < nch - 1) { CP_WAIT(1); } else { CP_WAIT(0); }
        __syncthreads();

        if (i + 2 < nch) { fillA(i + 2, nbuf); loadV(i + 2, nbuf); }
        CP_COMMIT();

        const uint32_t ab = sAaddr + buf * FTILE;
        const uint32_t bb = sBaddr + buf * FTILE;
        #pragma unroll
        for (int ks = 0; ks < 3; ks++) {
            uint32_t af[4][4], bfr[2][4];
            #pragma unroll
            for (int fm = 0; fm < 4; fm++)
                ldsm4(af[fm], ab + ((aRow + fm * 16) * FPAD + ks * 16 + aK) * 2);
            #pragma unroll
            for (int bg = 0; bg < 2; bg++)
                ldsm4(bfr[bg], bb + ((bRow + bg * 16) * FPAD + ks * 16 + bK) * 2);
            #pragma unroll
            for (int fm = 0; fm < 4; fm++)
                #pragma unroll
                for (int fn = 0; fn < 4; fn++)
                    mma16816(acc[fm][fn], af[fm], &bfr[fn >> 1][(fn & 1) * 2]);
        }

        buf = (buf == 2) ? 0 : buf + 1;
        nbuf = (nbuf == 2) ? 0 : nbuf + 1;
    }

    // ---- row sums -> 1/l ----
    __syncthreads();
    sums[t] = sumReg;
    __syncthreads();
    if (t < 128) mrow[t] = 1.0f / (sums[2 * t] + sums[2 * t + 1]);
    __syncthreads();

    // ---- epilogue: O *= 1/l, triple-split to Y3 ----
    const int g = lane >> 2, tg = lane & 3;
    #pragma unroll
    for (int fm = 0; fm < 4; fm++) {
        #pragma unroll
        for (int fn = 0; fn < 4; fn++) {
            const int col = nBase + fn * 8 + tg * 2;
            #pragma unroll
            for (int half = 0; half < 2; half++) {
                const int row = mBase + fm * 16 + g + half * 8;
                const float inv = mrow[row];
                float v0 = acc[fm][fn][half * 2]     * inv;
                float v1 = acc[fm][fn][half * 2 + 1] * inv;
                bf16 h0, l0, h1, l1;
                split2(v0, h0, l0); split2(v1, h1, l1);
                uint32_t* dst = reinterpret_cast<uint32_t*>(
                    Yb + (long long)(m0 + row) * 3 * DMODEL + 3 * col);
                dst[0] = pk(h0, l0);
                dst[1] = pk(h0, h1);
                dst[2] = pk(l1, h1);
            }
        }
    }
}

// ---------------- fp32 -> triple-interleaved bf16 ----------------
template<bool ASIDE>
__global__ void split3_kernel(const float* __restrict__ in, bf16* __restrict__ o3, long long n4)
{
    long long i = (long long)blockIdx.x * blockDim.x + threadIdx.x;
    if (i >= n4) return;
    float4 v = reinterpret_cast<const float4*>(in)[i];
    bf16 h[4], l[4];
    split2(v.x, h[0], l[0]); split2(v.y, h[1], l[1]);
    split2(v.z, h[2], l[2]); split2(v.w, h[3], l[3]);
    uint32_t u[6];
    if (ASIDE) {
        u[0] = pk(h[0], l[0]); u[1] = pk(h[0], h[1]); u[2] = pk(l[1], h[1]);
        u[3] = pk(h[2], l[2]); u[4] = pk(h[2], h[3]); u[5] = pk(l[3], h[3]);
    } else {
        u[0] = pk(h[0], h[0]); u[1] = pk(l[0], h[1]); u[2] = pk(h[1], l[1]);
        u[3] = pk(h[2], h[2]); u[4] = pk(l[2], h[3]); u[5] = pk(h[3], l[3]);
    }
    uint2* dst = reinterpret_cast<uint2*>(o3 + i * 12);
    dst[0] = make_uint2(u[0], u[1]);
    dst[1] = make_uint2(u[2], u[3]);
    dst[2] = make_uint2(u[4], u[5]);
}

// ---------------- RMSNorm + RoPE + gain -> triple bf16 [b,h,s,3d] ----------------
template<bool ASIDE>
__global__ void postproc_qk(const float* __restrict__ in, bf16* __restrict__ o3,
                            const float* __restrict__ gain, int nHeads)
{
    const int m = blockIdx.x, h = blockIdx.y, d = threadIdx.x;
    const int b = m / SEQ, s = m % SEQ;
    float v = in[(long long)m * (nHeads * HD) + h * HD + d];

    __shared__ float red[128];
    __shared__ float vec[128];
    red[d] = v * v;
    __syncthreads();
    #pragma unroll
    for (int off = 64; off > 0; off >>= 1) {
        if (d < off) red[d] += red[d + off];
        __syncthreads();
    }
    float ms = red[0] * (1.0f / 128.0f);
    v = v * rsqrtf(ms + EPSV);
    vec[d] = v;
    __syncthreads();
    if (d < ROPE) {
        int j = d & 31;
        float inv_freq = powf(10000.0f, -(float)j / 32.0f);
        float ang = (float)s * inv_freq;
        float c = cosf(ang), sn = sinf(ang);
        float x1 = vec[j], x2 = vec[j + 32];
        v = (d < 32) ? (x1 * c + x2 * sn) : (-x1 * sn + x2 * c);
    }
    if (gain) v *= gain[h];

    bf16 hh, ll; split2(v, hh, ll);
    bf16* o = o3 + ((long long)(b * nHeads + h) * SEQ + s) * (3 * HD) + 3 * d;
    if (ASIDE) { o[0] = hh; o[1] = ll; o[2] = hh; }
    else       { o[0] = hh; o[1] = hh; o[2] = ll; }
}

// ---------------- V: split + transpose to [b,kv,d,3s] (B-side) ----------------
__global__ void transpose_v(const float* __restrict__ in, bf16* __restrict__ o3)
{
    const int m = blockIdx.x, h = blockIdx.y, d = threadIdx.x;
    const int b = m / SEQ, s = m % SEQ;
    float v = in[(long long)m * (NKV * HD) + h * HD + d];
    bf16 hh, ll; split2(v, hh, ll);
    bf16* o = o3 + ((long long)(b * NKV + h) * HD + d) * (3 * SEQ) + 3 * s;
    o[0] = hh; o[1] = hh; o[2] = ll;
}

// ---------------- launch ----------------
extern "C" void kernel_launch(void* const* d_in, const int* in_sizes, int n_in,
                              void* d_out, int out_size)
{
    const float* x     = (const float*)d_in[0];
    const float* q_w   = (const float*)d_in[1];
    const float* k_w   = (const float*)d_in[2];
    const float* v_w   = (const float*)d_in[3];
    const float* out_w = (const float*)d_in[4];
    const float* q_g   = (const float*)d_in[5];
    float* out = (float*)d_out;

    static bool init = false;
    static bf16 *x3,*qw3,*kw3,*vw3,*ow3,*Qp3,*Kp3,*Vt3,*Y3;
    static float *Qb,*Kb,*Vb,*Sb;
    if (!init) {
        cudaGetSymbolAddress((void**)&x3,  g_x3);
        cudaGetSymbolAddress((void**)&qw3, g_qw3);
        cudaGetSymbolAddress((void**)&kw3, g_kw3);
        cudaGetSymbolAddress((void**)&vw3, g_vw3);
        cudaGetSymbolAddress((void**)&ow3, g_ow3);
        cudaGetSymbolAddress((void**)&Qb,  g_Qb);
        cudaGetSymbolAddress((void**)&Kb,  g_Kb);
        cudaGetSymbolAddress((void**)&Vb,  g_Vb);
        cudaGetSymbolAddress((void**)&Qp3, g_Qp3);
        cudaGetSymbolAddress((void**)&Kp3, g_Kp3);
        cudaGetSymbolAddress((void**)&Vt3, g_Vt3);
        cudaGetSymbolAddress((void**)&Sb,  g_S);
        cudaGetSymbolAddress((void**)&Y3,  g_Y3);
        cudaFuncSetAttribute(mm_kernel<false,false>, cudaFuncAttributeMaxDynamicSharedMemorySize, MM_SMEM);
        cudaFuncSetAttribute(mm_kernel<true, false>, cudaFuncAttributeMaxDynamicSharedMemorySize, MM_SMEM);
        cudaFuncSetAttribute(pv_fused, cudaFuncAttributeMaxDynamicSharedMemorySize, FV_SMEM);
        init = true;
    }

    const long long SS = (long long)SEQ * SEQ;
    // scores pre-scaled by log2(e) so downstream uses exp2
    const float scale2 = 0.08838834764831845f * 1.4426950408889634f;

    {
        long long n4;
        n4 = (long long)MTOK * DMODEL / 4;   split3_kernel<true ><<<(unsigned)((n4+255)/256),256>>>(x, x3, n4);
        n4 = (long long)DMODEL * DMODEL / 4; split3_kernel<false><<<(unsigned)((n4+255)/256),256>>>(q_w, qw3, n4);
        n4 = (long long)NKV*HD * DMODEL / 4; split3_kernel<false><<<(unsigned)((n4+255)/256),256>>>(k_w, kw3, n4);
        n4 = (long long)NKV*HD * DMODEL / 4; split3_kernel<false><<<(unsigned)((n4+255)/256),256>>>(v_w, vw3, n4);
        n4 = (long long)DMODEL * DMODEL / 4; split3_kernel<false><<<(unsigned)((n4+255)/256),256>>>(out_w, ow3, n4);
    }

    // QKV projections (fp32 out), K3 = 3*DMODEL
    mm_kernel<false,false><<<dim3(DMODEL/128, MTOK/128, 1), 256, MM_SMEM>>>(
        x3, qw3, Qb, nullptr, 3*DMODEL, 3*DMODEL, 3*DMODEL, DMODEL, 0,0,0,0, 1,1, 1.0f);
    mm_kernel<false,false><<<dim3((NKV*HD)/128, MTOK/128, 1), 256, MM_SMEM>>>(
        x3, kw3, Kb, nullptr, 3*DMODEL, 3*DMODEL, 3*DMODEL, NKV*HD, 0,0,0,0, 1,1, 1.0f);
    mm_kernel<false,false><<<dim3((NKV*HD)/128, MTOK/128, 1), 256, MM_SMEM>>>(
        x3, vw3, Vb, nullptr, 3*DMODEL, 3*DMODEL, 3*DMODEL, NKV*HD, 0,0,0,0, 1,1, 1.0f);

    postproc_qk<true ><<<dim3(MTOK, NH),  128>>>(Qb, Qp3, q_g,     NH);
    postproc_qk<false><<<dim3(MTOK, NKV), 128>>>(Kb, Kp3, nullptr, NKV);
    transpose_v<<<dim3(MTOK, NKV), 128>>>(Vb, Vt3);

    // scores = Qp @ Kp^T * scale * log2e, causal. K3 = 384
    mm_kernel<true,false><<<dim3(SEQ/128, SEQ/128, BATCH*NH), 256, MM_SMEM>>>(
        Qp3, Kp3, Sb, nullptr, 3*HD, 3*HD, 3*HD, SEQ,
        (long long)SEQ*3*HD, (long long)SEQ*3*HD, SS, 0, 4, 1, scale2);

    // fused softmax + P@V -> Y3 triple bf16
    pv_fused<<<dim3(BATCH*NH, SEQ/128, 1), 256, FV_SMEM>>>(Sb, Vt3, Y3);

    // out = Y @ out_w^T (fp32 into d_out)
    mm_kernel<false,false><<<dim3(DMODEL/128, MTOK/128, 1), 256, MM_SMEM>>>(
        Y3, ow3, out, nullptr, 3*DMODEL, 3*DMODEL, 3*DMODEL, DMODEL, 0,0,0,0, 1,1, 1.0f);
}